// round 10
// baseline (speedup 1.0000x reference)
#include <cuda_runtime.h>
#include <cuda_bf16.h>
#include <cstdint>

// Problem constants
#define BB 2
#define SS 2048
#define DD 1024
#define HH 16
#define HD 64
#define N3 3072
#define MROWS 4096

// d_out layout
#define A_SZ   ((long long)BB * SS * DD)
#define P_HALF ((long long)BB * HH * SS * HD)
#define P_OFF  (A_SZ)
#define ATTN_OFF (A_SZ + 2 * P_HALF)

#define QKV_N (BB * HH * SS * HD)

// Scratch (device globals)
__device__ signed char gx1[MROWS * DD], gx2[MROWS * DD];
__device__ float gxsc[MROWS];
__device__ signed char gwa1[N3 * DD], gwa2[N3 * DD];
__device__ float gwasc[N3];
__device__ signed char gwp1[DD * DD], gwp2[DD * DD];
__device__ float gwpsc[DD];
__device__ float g_ah[MROWS * DD];
__device__ signed char gah1[MROWS * DD], gah2[MROWS * DD];
__device__ float gahsc[MROWS];
__device__ signed char gq1[QKV_N], gq2[QKV_N], gk1[QKV_N], gk2[QKV_N];
__device__ float gqsc[BB * HH * SS], gksc[BB * HH * SS];
__device__ __nv_bfloat16 g_vh[QKV_N], g_vl[QKV_N];

// ====================== base-PTX helpers ====================================
__device__ __forceinline__ uint32_t smem_u32(const void* p) {
    uint32_t a;
    asm("{ .reg .u64 t; cvta.to.shared.u64 t, %1; cvt.u32.u64 %0, t; }"
        : "=r"(a) : "l"(p));
    return a;
}
__device__ __forceinline__ void cpa16(uint32_t s, const void* g) {
    asm volatile("cp.async.cg.shared.global [%0], [%1], 16;" :: "r"(s), "l"(g));
}
#define CP_COMMIT() asm volatile("cp.async.commit_group;" ::: "memory")
#define CP_WAIT(n)  asm volatile("cp.async.wait_group %0;" :: "n"(n) : "memory")

__device__ __forceinline__ void ldsm4(uint32_t* r, uint32_t a) {
    asm volatile("ldmatrix.sync.aligned.m8n8.x4.shared.b16 {%0,%1,%2,%3}, [%4];"
                 : "=r"(r[0]), "=r"(r[1]), "=r"(r[2]), "=r"(r[3]) : "r"(a));
}
__device__ __forceinline__ void ldsm2(uint32_t* r, uint32_t a) {
    asm volatile("ldmatrix.sync.aligned.m8n8.x2.shared.b16 {%0,%1}, [%2];"
                 : "=r"(r[0]), "=r"(r[1]) : "r"(a));
}
__device__ __forceinline__ void ldsm2t(uint32_t* r, uint32_t a) {
    asm volatile("ldmatrix.sync.aligned.m8n8.x2.trans.shared.b16 {%0,%1}, [%2];"
                 : "=r"(r[0]), "=r"(r[1]) : "r"(a));
}
__device__ __forceinline__ void mma_bf16(float* d, const uint32_t* a, const uint32_t* b) {
    asm volatile("mma.sync.aligned.m16n8k16.row.col.f32.bf16.bf16.f32 "
                 "{%0,%1,%2,%3}, {%4,%5,%6,%7}, {%8,%9}, {%0,%1,%2,%3};"
                 : "+f"(d[0]), "+f"(d[1]), "+f"(d[2]), "+f"(d[3])
                 : "r"(a[0]), "r"(a[1]), "r"(a[2]), "r"(a[3]), "r"(b[0]), "r"(b[1]));
}
__device__ __forceinline__ void mma_s8(int* d, const uint32_t* a, const uint32_t* b) {
    asm volatile("mma.sync.aligned.m16n8k32.row.col.s32.s8.s8.s32 "
                 "{%0,%1,%2,%3}, {%4,%5,%6,%7}, {%8,%9}, {%0,%1,%2,%3};"
                 : "+r"(d[0]), "+r"(d[1]), "+r"(d[2]), "+r"(d[3])
                 : "r"(a[0]), "r"(a[1]), "r"(a[2]), "r"(a[3]), "r"(b[0]), "r"(b[1]));
}
__device__ __forceinline__ void sp(float x, uint16_t& h, uint16_t& l) {
    __nv_bfloat16 bh = __float2bfloat16_rn(x);
    h = __bfloat16_as_ushort(bh);
    l = __bfloat16_as_ushort(__float2bfloat16_rn(x - __bfloat162float(bh)));
}
__device__ __forceinline__ uint32_t pk(uint16_t a, uint16_t b) {
    return (uint32_t)a | ((uint32_t)b << 16);
}
// two-digit int8 quantization: v*inv = d1 + d2/256 + eps
__device__ __forceinline__ void q8(float v, float inv, int& d1, int& d2) {
    float t = v * inv;
    float r1 = rintf(t);
    d1 = (int)r1;
    int dd2 = (int)rintf((t - r1) * 256.f);
    d2 = dd2 > 127 ? 127 : dd2;
}
__device__ __forceinline__ uint32_t pb4(int a, int b, int c, int d) {
    return ((uint32_t)(uint8_t)(signed char)a) | ((uint32_t)(uint8_t)(signed char)b << 8) |
           ((uint32_t)(uint8_t)(signed char)c << 16) | ((uint32_t)(uint8_t)(signed char)d << 24);
}
__device__ __forceinline__ uint16_t pb2(int a, int b) {
    return (uint16_t)(((uint32_t)(uint8_t)(signed char)a) |
                      ((uint32_t)(uint8_t)(signed char)b << 8));
}

// ====================== preprocessing kernels ===============================
// rows of length 1024: quantize to 2 int8 digits + per-row scale
__global__ __launch_bounds__(256) void split_q8_rows(const float* __restrict__ in,
                                                     signed char* __restrict__ d1,
                                                     signed char* __restrict__ d2,
                                                     float* __restrict__ sc) {
    __shared__ float wmax[8];
    const int row = blockIdx.x, tid = threadIdx.x;
    const int lane = tid & 31, warp = tid >> 5;
    float4 v = ((const float4*)(in + (long long)row * 1024))[tid];
    float m = fmaxf(fmaxf(fabsf(v.x), fabsf(v.y)), fmaxf(fabsf(v.z), fabsf(v.w)));
#pragma unroll
    for (int off = 16; off; off >>= 1) m = fmaxf(m, __shfl_xor_sync(0xFFFFFFFFu, m, off));
    if (lane == 0) wmax[warp] = m;
    __syncthreads();
    float M = 1e-20f;
#pragma unroll
    for (int i = 0; i < 8; i++) M = fmaxf(M, wmax[i]);
    if (tid == 0) sc[row] = M * (1.f / 127.f);
    float inv = 127.f / M;
    int a1, a2, b1, b2, c1, c2, e1, e2;
    q8(v.x, inv, a1, a2); q8(v.y, inv, b1, b2);
    q8(v.z, inv, c1, c2); q8(v.w, inv, e1, e2);
    ((uint32_t*)d1)[row * 256 + tid] = pb4(a1, b1, c1, e1);
    ((uint32_t*)d2)[row * 256 + tid] = pb4(a2, b2, c2, e2);
}

// per-column max of w[1024][N] -> sc[c] = max/127
__global__ __launch_bounds__(256) void colmax_k(const float* __restrict__ w,
                                                float* __restrict__ sc, int N) {
    int c = blockIdx.x * 256 + threadIdx.x;
    if (c >= N) return;
    float m = 1e-20f;
    for (int r = 0; r < 1024; r++) m = fmaxf(m, fabsf(w[(long long)r * N + c]));
    sc[c] = m * (1.f / 127.f);
}

// transpose + quantize: w[1024][N] -> d[N][1024] int8 digits (per out-row scale)
__global__ __launch_bounds__(256) void tq_k(const float* __restrict__ in,
                                            signed char* __restrict__ d1,
                                            signed char* __restrict__ d2,
                                            const float* __restrict__ sc, int N) {
    __shared__ float t[32][33];
    int nb = blockIdx.x * 32, kb = blockIdx.y * 32;
#pragma unroll
    for (int r = 0; r < 4; r++)
        t[threadIdx.y + r * 8][threadIdx.x] =
            in[(long long)(kb + threadIdx.y + r * 8) * N + nb + threadIdx.x];
    __syncthreads();
#pragma unroll
    for (int r = 0; r < 4; r++) {
        int n = nb + threadIdx.y + r * 8;
        float inv = 1.f / sc[n];
        float v = t[threadIdx.x][threadIdx.y + r * 8];
        int q1, q2;
        q8(v, inv, q1, q2);
        long long o = (long long)n * 1024 + kb + threadIdx.x;
        d1[o] = (signed char)q1;
        d2[o] = (signed char)q2;
    }
}

// ====================== int8 GEMM (two-digit) ===============================
// D[128,128] = A[128,1024] @ B[N,1024]^T, per-row scales both sides.
#define G8PB 80
#define G8_TILEB (128 * G8PB)          // 10240
#define G8_STAGEB (4 * G8_TILEB)       // 40960
#define G8_SMEM (2 * G8_STAGEB)        // 81920

template <int MODE>
__global__ __launch_bounds__(256) void gemm_q8(
    const signed char* __restrict__ A1, const signed char* __restrict__ A2,
    const float* __restrict__ Asc,
    const signed char* __restrict__ B1, const signed char* __restrict__ B2,
    const float* __restrict__ Bsc,
    const float* __restrict__ bias, float* __restrict__ out) {
    extern __shared__ char smm[];
    const uint32_t sb = smem_u32(smm);
    const int tid = threadIdx.x;
    const int lane = tid & 31, warp = tid >> 5;
    const int wm = warp >> 1, wn = warp & 1;
    const int qr = lane >> 2, qc2 = (lane & 3) * 2;
    const int nbase = blockIdx.x * 128, rbase = blockIdx.y * 128;

    int o1[2][8][4], o2[2][8][4];
#pragma unroll
    for (int a = 0; a < 2; a++)
#pragma unroll
        for (int b = 0; b < 8; b++)
#pragma unroll
            for (int c = 0; c < 4; c++) { o1[a][b][c] = 0; o2[a][b][c] = 0; }

    const char* srcs[4] = {
        (const char*)(A1 + (long long)rbase * 1024),
        (const char*)(A2 + (long long)rbase * 1024),
        (const char*)(B1 + (long long)nbase * 1024),
        (const char*)(B2 + (long long)nbase * 1024)};

    // prologue: stage 0 (4 tiles x 128 rows x 64B)
#pragma unroll
    for (int i = 0; i < 8; i++) {
        int idx = tid + i * 256;
        int t = idx >> 9, q = idx & 511, r = q >> 2, c = q & 3;
        cpa16(sb + t * G8_TILEB + r * G8PB + c * 16,
              srcs[t] + (long long)r * 1024 + c * 16);
    }
    CP_COMMIT();

    for (int ks = 0; ks < 16; ks++) {
        if (ks + 1 < 16) {
            const int kboff = (ks + 1) * 64;
            const uint32_t dstb = sb + ((ks + 1) & 1) * G8_STAGEB;
#pragma unroll
            for (int i = 0; i < 8; i++) {
                int idx = tid + i * 256;
                int t = idx >> 9, q = idx & 511, r = q >> 2, c = q & 3;
                cpa16(dstb + t * G8_TILEB + r * G8PB + c * 16,
                      srcs[t] + (long long)r * 1024 + kboff + c * 16);
            }
            CP_COMMIT();
            CP_WAIT(1);
        } else {
            CP_WAIT(0);
        }
        __syncthreads();

        const uint32_t base = sb + (ks & 1) * G8_STAGEB;
#pragma unroll
        for (int j = 0; j < 2; j++) {   // two k32 slices per 64-byte chunk
            uint32_t a1f[2][4], a2f[2][4];
#pragma unroll
            for (int mt = 0; mt < 2; mt++) {
                uint32_t r = wm * 32 + mt * 16 + (lane & 7) + ((lane >> 3) & 1) * 8;
                uint32_t c = j * 32 + (lane >> 4) * 16;
                uint32_t off = r * G8PB + c;
                ldsm4(a1f[mt], base + off);
                ldsm4(a2f[mt], base + G8_TILEB + off);
            }
            uint32_t b1f[8][2], b2f[8][2];
#pragma unroll
            for (int nt = 0; nt < 8; nt++) {
                uint32_t n = wn * 64 + nt * 8 + (lane & 7);
                uint32_t c = j * 32 + ((lane >> 3) & 1) * 16;
                uint32_t off = n * G8PB + c;
                ldsm2(b1f[nt], base + 2 * G8_TILEB + off);
                ldsm2(b2f[nt], base + 3 * G8_TILEB + off);
            }
#pragma unroll
            for (int nt = 0; nt < 8; nt++) {
                mma_s8(o1[0][nt], a1f[0], b1f[nt]);
                mma_s8(o1[1][nt], a1f[1], b1f[nt]);
            }
#pragma unroll
            for (int nt = 0; nt < 8; nt++) {
                mma_s8(o2[0][nt], a1f[0], b2f[nt]);
                mma_s8(o2[1][nt], a1f[1], b2f[nt]);
            }
#pragma unroll
            for (int nt = 0; nt < 8; nt++) {
                mma_s8(o2[0][nt], a2f[0], b1f[nt]);
                mma_s8(o2[1][nt], a2f[1], b1f[nt]);
            }
        }
        __syncthreads();
    }

    // epilogue (per warp: columns = one 64-col block = one head when MODE 0)
    const int colblk = nbase + wn * 64;
#pragma unroll
    for (int mt = 0; mt < 2; mt++) {
        const int r0 = rbase + wm * 32 + mt * 16 + qr;
        const int r1 = r0 + 8;
        const float sa0 = Asc[r0], sa1 = Asc[r1];
        float v0[16], v1[16];
#pragma unroll
        for (int nt = 0; nt < 8; nt++) {
#pragma unroll
            for (int c2 = 0; c2 < 2; c2++) {
                const int cg = colblk + nt * 8 + qc2 + c2;
                const float sbv = Bsc[cg];
                const float bi = bias[cg];
                v0[nt * 2 + c2] = sa0 * sbv *
                    ((float)o1[mt][nt][c2] + (float)o2[mt][nt][c2] * 0.00390625f) + bi;
                v1[nt * 2 + c2] = sa1 * sbv *
                    ((float)o1[mt][nt][2 + c2] + (float)o2[mt][nt][2 + c2] * 0.00390625f) + bi;
            }
        }
        if (MODE == 1) {
#pragma unroll
            for (int nt = 0; nt < 8; nt++) {
                const int cg = colblk + nt * 8 + qc2;
                *(float2*)&out[(long long)r0 * DD + cg] = make_float2(v0[nt * 2], v0[nt * 2 + 1]);
                *(float2*)&out[(long long)r1 * DD + cg] = make_float2(v1[nt * 2], v1[nt * 2 + 1]);
            }
        } else {
            const int which = colblk >> 10;
            const int head = (colblk >> 6) & 15;
            const int b_0 = r0 >> 11, s_0 = r0 & 2047;
            const int b_1 = r1 >> 11, s_1 = r1 & 2047;
            const long long hb0 = ((long long)(b_0 * HH + head)) * SS + s_0;
            const long long hb1 = ((long long)(b_1 * HH + head)) * SS + s_1;
            const long long i0 = hb0 * HD, i1 = hb1 * HD;
            if (which == 2) {
                // v: fp32 present + bf16 hi/lo for AV
#pragma unroll
                for (int nt = 0; nt < 8; nt++) {
                    const int e0 = nt * 8 + qc2;
                    *(float2*)&out[P_OFF + P_HALF + i0 + e0] = make_float2(v0[nt * 2], v0[nt * 2 + 1]);
                    *(float2*)&out[P_OFF + P_HALF + i1 + e0] = make_float2(v1[nt * 2], v1[nt * 2 + 1]);
                    uint16_t h0, h1, h2, h3, l0, l1, l2, l3;
                    sp(v0[nt * 2], h0, l0); sp(v0[nt * 2 + 1], h1, l1);
                    sp(v1[nt * 2], h2, l2); sp(v1[nt * 2 + 1], h3, l3);
                    *(uint32_t*)&g_vh[i0 + e0] = pk(h0, h1);
                    *(uint32_t*)&g_vl[i0 + e0] = pk(l0, l1);
                    *(uint32_t*)&g_vh[i1 + e0] = pk(h2, h3);
                    *(uint32_t*)&g_vl[i1 + e0] = pk(l2, l3);
                }
            } else {
                // q or k: quantize per (row, head) with warp rowmax
                float m0 = 1e-20f, m1 = 1e-20f;
#pragma unroll
                for (int i = 0; i < 16; i++) {
                    m0 = fmaxf(m0, fabsf(v0[i]));
                    m1 = fmaxf(m1, fabsf(v1[i]));
                }
                m0 = fmaxf(m0, __shfl_xor_sync(0xFFFFFFFFu, m0, 1));
                m0 = fmaxf(m0, __shfl_xor_sync(0xFFFFFFFFu, m0, 2));
                m1 = fmaxf(m1, __shfl_xor_sync(0xFFFFFFFFu, m1, 1));
                m1 = fmaxf(m1, __shfl_xor_sync(0xFFFFFFFFu, m1, 2));
                const float inv0 = 127.f / m0, inv1 = 127.f / m1;
                signed char* d1 = (which == 0) ? gq1 : gk1;
                signed char* d2 = (which == 0) ? gq2 : gk2;
                float* scp = (which == 0) ? gqsc : gksc;
                if ((lane & 3) == 0) {
                    scp[hb0] = m0 * (1.f / 127.f);
                    scp[hb1] = m1 * (1.f / 127.f);
                }
#pragma unroll
                for (int nt = 0; nt < 8; nt++) {
                    const int e0 = nt * 8 + qc2;
                    if (which == 1) {
                        *(float2*)&out[P_OFF + i0 + e0] = make_float2(v0[nt * 2], v0[nt * 2 + 1]);
                        *(float2*)&out[P_OFF + i1 + e0] = make_float2(v1[nt * 2], v1[nt * 2 + 1]);
                    }
                    int a1, a2, b1, b2;
                    q8(v0[nt * 2], inv0, a1, a2); q8(v0[nt * 2 + 1], inv0, b1, b2);
                    *(uint16_t*)&d1[i0 + e0] = pb2(a1, b1);
                    *(uint16_t*)&d2[i0 + e0] = pb2(a2, b2);
                    q8(v1[nt * 2], inv1, a1, a2); q8(v1[nt * 2 + 1], inv1, b1, b2);
                    *(uint16_t*)&d1[i1 + e0] = pb2(a1, b1);
                    *(uint16_t*)&d2[i1 + e0] = pb2(a2, b2);
                }
            }
        }
    }
}

// ====================== attention (int8 QK, bf16 AV) ========================
#define APB 144
#define A8PB 80
#define Q8T (128 * A8PB)               // 10240 per digit
#define K8T (64 * A8PB)                // 5120 per digit
#define VTB (64 * APB)                 // 9216 per digit
#define ST_VH (2 * K8T)                // 10240
#define ST_VL (ST_VH + VTB)            // 19456
#define ST_KS (ST_VL + VTB)            // 28672
#define KSTG (ST_KS + 256)             // 28928
#define KB0 (2 * Q8T)                  // 20480
#define ATTN_SMEM (KB0 + 2 * KSTG)     // 78336

__global__ __launch_bounds__(256) void attn_q8(float* __restrict__ out) {
    extern __shared__ char smm[];
    const uint32_t sb = smem_u32(smm);
    const int tid = threadIdx.x;
    const int lane = tid & 31, wm = tid >> 5;
    const int qr = lane >> 2, qc2 = (lane & 3) * 2;
    const int qt = (gridDim.x - 1) - blockIdx.x;
    const int h = blockIdx.y, b = blockIdx.z;
    const int qbase = qt * 128;
    const int bh_ = b * HH + h;
    const long long hoff = (long long)bh_ * SS * HD;
    const signed char* q1g = gq1 + hoff + (long long)qbase * HD;
    const signed char* q2g = gq2 + hoff + (long long)qbase * HD;
    const signed char* k1g = gk1 + hoff;
    const signed char* k2g = gk2 + hoff;
    const char* vhg = (const char*)(g_vh + hoff);
    const char* vlg = (const char*)(g_vl + hoff);
    const float* kscg = gksc + (long long)bh_ * SS;
    float* attn_out = out + ATTN_OFF + (long long)bh_ * SS * SS;
    const int nkt = 2 * qt + 2;

    // issue Q digit loads
#pragma unroll
    for (int i = 0; i < 4; i++) {
        int idx = tid + i * 256;
        int d = idx >> 9, q = idx & 511, r = q >> 2, c = q & 3;
        cpa16(sb + d * Q8T + r * A8PB + c * 16,
              (d ? q2g : q1g) + (long long)r * HD + c * 16);
    }
    CP_COMMIT();

    // K tile 0 (+scales) into stage 0
    {
        const uint32_t db = sb + KB0;
#pragma unroll
        for (int i = 0; i < 3; i++) {
            int idx = tid + i * 256;
            if (idx < 512) {
                int d = idx >> 8, q = idx & 255, r = q >> 2, c = q & 3;
                cpa16(db + d * K8T + r * A8PB + c * 16,
                      (d ? k2g : k1g) + (long long)r * HD + c * 16);
            } else if (idx < 528) {
                int c = idx - 512;
                cpa16(db + ST_KS + c * 16, (const char*)kscg + c * 16);
            }
        }
    }
    CP_COMMIT();

    // zero-fill this CTA's strictly-upper attn region (overlaps with loads)
    {
        const int Lc = (qt + 1) * 128;
        if (Lc < SS) {
            const int per4 = (SS - Lc) >> 2;
            const float4 z = make_float4(0.f, 0.f, 0.f, 0.f);
            for (int i = tid; i < 128 * per4; i += 256) {
                int r = i / per4;
                int c = Lc + (i - r * per4) * 4;
                *(float4*)&attn_out[(long long)(qbase + r) * SS + c] = z;
            }
        }
    }
    CP_WAIT(0);
    __syncthreads();

    // Q fragments (2 k32 slices x 2 digits)
    uint32_t q1f[2][4], q2f[2][4];
#pragma unroll
    for (int j = 0; j < 2; j++) {
        uint32_t r = wm * 16 + (lane & 7) + ((lane >> 3) & 1) * 8;
        uint32_t c = j * 32 + (lane >> 4) * 16;
        uint32_t off = r * A8PB + c;
        ldsm4(q1f[j], sb + off);
        ldsm4(q2f[j], sb + Q8T + off);
    }

    const int r0g = qbase + wm * 16 + qr;
    const int r1g = r0g + 8;
    const float sq0 = gqsc[(long long)bh_ * SS + r0g] * 0.125f;
    const float sq1 = gqsc[(long long)bh_ * SS + r1g] * 0.125f;

    // ---------------- pass A: rowsums ----------------
    float rs0 = 0.f, rs1 = 0.f;
    for (int kt = 0; kt < nkt; kt++) {
        if (kt + 1 < nkt) {
            const uint32_t db = sb + KB0 + ((kt + 1) & 1) * KSTG;
            const long long go = (long long)(kt + 1) * 64 * HD;
#pragma unroll
            for (int i = 0; i < 3; i++) {
                int idx = tid + i * 256;
                if (idx < 512) {
                    int d = idx >> 8, q = idx & 255, r = q >> 2, c = q & 3;
                    cpa16(db + d * K8T + r * A8PB + c * 16,
                          (d ? k2g : k1g) + go + (long long)r * HD + c * 16);
                } else if (idx < 528) {
                    int c = idx - 512;
                    cpa16(db + ST_KS + c * 16,
                          (const char*)(kscg + (kt + 1) * 64) + c * 16);
                }
            }
            CP_COMMIT();
            CP_WAIT(1);
        } else {
            CP_WAIT(0);
        }
        __syncthreads();

        const uint32_t kb = sb + KB0 + (kt & 1) * KSTG;
        const float* ksm = (const float*)(smm + KB0 + (kt & 1) * KSTG + ST_KS);
        int s1[8][4], s2[8][4];
#pragma unroll
        for (int nt = 0; nt < 8; nt++)
#pragma unroll
            for (int c = 0; c < 4; c++) { s1[nt][c] = 0; s2[nt][c] = 0; }
#pragma unroll
        for (int j = 0; j < 2; j++) {
            uint32_t b1f[8][2], b2f[8][2];
#pragma unroll
            for (int nt = 0; nt < 8; nt++) {
                uint32_t n = nt * 8 + (lane & 7);
                uint32_t c = j * 32 + ((lane >> 3) & 1) * 16;
                uint32_t off = n * A8PB + c;
                ldsm2(b1f[nt], kb + off);
                ldsm2(b2f[nt], kb + K8T + off);
            }
#pragma unroll
            for (int nt = 0; nt < 8; nt++) mma_s8(s1[nt], q1f[j], b1f[nt]);
#pragma unroll
            for (int nt = 0; nt < 8; nt++) mma_s8(s2[nt], q1f[j], b2f[nt]);
#pragma unroll
            for (int nt = 0; nt < 8; nt++) mma_s8(s2[nt], q2f[j], b1f[nt]);
        }
#pragma unroll
        for (int nt = 0; nt < 8; nt++) {
            const int cg = kt * 64 + nt * 8 + qc2;
            const float sk0 = ksm[nt * 8 + qc2], sk1 = ksm[nt * 8 + qc2 + 1];
            if (cg <= r0g)
                rs0 += __expf(sq0 * sk0 * ((float)s1[nt][0] + (float)s2[nt][0] * 0.00390625f));
            if (cg + 1 <= r0g)
                rs0 += __expf(sq0 * sk1 * ((float)s1[nt][1] + (float)s2[nt][1] * 0.00390625f));
            if (cg <= r1g)
                rs1 += __expf(sq1 * sk0 * ((float)s1[nt][2] + (float)s2[nt][2] * 0.00390625f));
            if (cg + 1 <= r1g)
                rs1 += __expf(sq1 * sk1 * ((float)s1[nt][3] + (float)s2[nt][3] * 0.00390625f));
        }
        __syncthreads();
    }
    rs0 += __shfl_xor_sync(0xFFFFFFFFu, rs0, 1);
    rs0 += __shfl_xor_sync(0xFFFFFFFFu, rs0, 2);
    rs1 += __shfl_xor_sync(0xFFFFFFFFu, rs1, 1);
    rs1 += __shfl_xor_sync(0xFFFFFFFFu, rs1, 2);
    const float ri0 = 1.0f / rs0;
    const float ri1 = 1.0f / rs1;

    // ---------------- pass B: write attn + A@V ----------------
    float o[8][4];
#pragma unroll
    for (int a = 0; a < 8; a++)
#pragma unroll
        for (int c = 0; c < 4; c++) o[a][c] = 0.f;

    // restart pipeline: K+V+scales tile 0 into stage 0
    {
        const uint32_t db = sb + KB0;
#pragma unroll
        for (int i = 0; i < 7; i++) {
            int idx = tid + i * 256;
            if (idx < 512) {
                int d = idx >> 8, q = idx & 255, r = q >> 2, c = q & 3;
                cpa16(db + d * K8T + r * A8PB + c * 16,
                      (d ? k2g : k1g) + (long long)r * HD + c * 16);
            } else if (idx < 1536) {
                int idx2 = idx - 512;
                int d = idx2 >> 9, q = idx2 & 511, r = q >> 3, c = q & 7;
                cpa16(db + (d ? ST_VL : ST_VH) + r * APB + c * 16,
                      (d ? vlg : vhg) + (long long)r * 128 + c * 16);
            } else if (idx < 1552) {
                int c = idx - 1536;
                cpa16(db + ST_KS + c * 16, (const char*)kscg + c * 16);
            }
        }
    }
    CP_COMMIT();

    for (int kt = 0; kt < nkt; kt++) {
        if (kt + 1 < nkt) {
            const uint32_t db = sb + KB0 + ((kt + 1) & 1) * KSTG;
            const long long go = (long long)(kt + 1) * 64 * HD;
            const long long gov = (long long)(kt + 1) * 64 * 128;
#pragma unroll
            for (int i = 0; i < 7; i++) {
                int idx = tid + i * 256;
                if (idx < 512) {
                    int d = idx >> 8, q = idx & 255, r = q >> 2, c = q & 3;
                    cpa16(db + d * K8T + r * A8PB + c * 16,
                          (d ? k2g : k1g) + go + (long long)r * HD + c * 16);
                } else if (idx < 1536) {
                    int idx2 = idx - 512;
                    int d = idx2 >> 9, q = idx2 & 511, r = q >> 3, c = q & 7;
                    cpa16(db + (d ? ST_VL : ST_VH) + r * APB + c * 16,
                          (d ? vlg : vhg) + gov + (long long)r * 128 + c * 16);
                } else if (idx < 1552) {
                    int c = idx - 1536;
                    cpa16(db + ST_KS + c * 16,
                          (const char*)(kscg + (kt + 1) * 64) + c * 16);
                }
            }
            CP_COMMIT();
            CP_WAIT(1);
        } else {
            CP_WAIT(0);
        }
        __syncthreads();

        const uint32_t kb = sb + KB0 + (kt & 1) * KSTG;
        const float* ksm = (const float*)(smm + KB0 + (kt & 1) * KSTG + ST_KS);
        int s1[8][4], s2[8][4];
#pragma unroll
        for (int nt = 0; nt < 8; nt++)
#pragma unroll
            for (int c = 0; c < 4; c++) { s1[nt][c] = 0; s2[nt][c] = 0; }
#pragma unroll
        for (int j = 0; j < 2; j++) {
            uint32_t b1f[8][2], b2f[8][2];
#pragma unroll
            for (int nt = 0; nt < 8; nt++) {
                uint32_t n = nt * 8 + (lane & 7);
                uint32_t c = j * 32 + ((lane >> 3) & 1) * 16;
                uint32_t off = n * A8PB + c;
                ldsm2(b1f[nt], kb + off);
                ldsm2(b2f[nt], kb + K8T + off);
            }
#pragma unroll
            for (int nt = 0; nt < 8; nt++) mma_s8(s1[nt], q1f[j], b1f[nt]);
#pragma unroll
            for (int nt = 0; nt < 8; nt++) mma_s8(s2[nt], q1f[j], b2f[nt]);
#pragma unroll
            for (int nt = 0; nt < 8; nt++) mma_s8(s2[nt], q2f[j], b1f[nt]);
        }

        uint32_t sah[4][4], sal[4][4];
#pragma unroll
        for (int nt = 0; nt < 8; nt++) {
            const int cg = kt * 64 + nt * 8 + qc2;
            const float sk0 = ksm[nt * 8 + qc2], sk1 = ksm[nt * 8 + qc2 + 1];
            float e0 = (cg > r0g) ? 0.f
                : __expf(sq0 * sk0 * ((float)s1[nt][0] + (float)s2[nt][0] * 0.00390625f)) * ri0;
            float e1 = (cg + 1 > r0g) ? 0.f
                : __expf(sq0 * sk1 * ((float)s1[nt][1] + (float)s2[nt][1] * 0.00390625f)) * ri0;
            float e2 = (cg > r1g) ? 0.f
                : __expf(sq1 * sk0 * ((float)s1[nt][2] + (float)s2[nt][2] * 0.00390625f)) * ri1;
            float e3 = (cg + 1 > r1g) ? 0.f
                : __expf(sq1 * sk1 * ((float)s1[nt][3] + (float)s2[nt][3] * 0.00390625f)) * ri1;
            *(float2*)&attn_out[(long long)r0g * SS + cg] = make_float2(e0, e1);
            *(float2*)&attn_out[(long long)r1g * SS + cg] = make_float2(e2, e3);
            uint16_t h0, h1, h2, h3, l0, l1, l2, l3;
            sp(e0, h0, l0); sp(e1, h1, l1); sp(e2, h2, l2); sp(e3, h3, l3);
            const int j = nt >> 1, half = (nt & 1) * 2;
            sah[j][half] = pk(h0, h1); sah[j][half + 1] = pk(h2, h3);
            sal[j][half] = pk(l0, l1); sal[j][half + 1] = pk(l2, l3);
        }
        // A@V (bf16 x3)
#pragma unroll
        for (int j = 0; j < 4; j++) {
            uint32_t vh2[8][2], vl2[8][2];
#pragma unroll
            for (int nt2 = 0; nt2 < 8; nt2++) {
                uint32_t key = j * 16 + ((lane >> 3) & 1) * 8 + (lane & 7);
                uint32_t off = key * APB + nt2 * 16;
                ldsm2t(vh2[nt2], kb + ST_VH + off);
                ldsm2t(vl2[nt2], kb + ST_VL + off);
            }
#pragma unroll
            for (int nt2 = 0; nt2 < 8; nt2++) mma_bf16(o[nt2], sah[j], vh2[nt2]);
#pragma unroll
            for (int nt2 = 0; nt2 < 8; nt2++) mma_bf16(o[nt2], sah[j], vl2[nt2]);
#pragma unroll
            for (int nt2 = 0; nt2 < 8; nt2++) mma_bf16(o[nt2], sal[j], vh2[nt2]);
        }
        __syncthreads();
    }

    // merged-head output -> fp32 scratch (quantized by split_q8_rows next)
#pragma unroll
    for (int nt2 = 0; nt2 < 8; nt2++) {
        const int col = h * 64 + nt2 * 8 + qc2;
        const long long gr0 = (long long)(b * SS + qbase + wm * 16 + qr);
        *(float2*)&g_ah[gr0 * DD + col] = make_float2(o[nt2][0], o[nt2][1]);
        *(float2*)&g_ah[(gr0 + 8) * DD + col] = make_float2(o[nt2][2], o[nt2][3]);
    }
}

// ====================== launch ==============================================
extern "C" void kernel_launch(void* const* d_in, const int* in_sizes, int n_in,
                              void* d_out, int out_size) {
    const float* x      = (const float*)d_in[0];
    const float* w_attn = (const float*)d_in[1];
    const float* b_attn = (const float*)d_in[2];
    const float* w_proj = (const float*)d_in[3];
    const float* b_proj = (const float*)d_in[4];
    float* out = (float*)d_out;

    signed char *x1, *x2, *wa1, *wa2, *wp1, *wp2, *ah1, *ah2;
    float *xsc, *wasc, *wpsc, *ahsc, *gah;
    cudaGetSymbolAddress((void**)&x1, gx1);   cudaGetSymbolAddress((void**)&x2, gx2);
    cudaGetSymbolAddress((void**)&xsc, gxsc);
    cudaGetSymbolAddress((void**)&wa1, gwa1); cudaGetSymbolAddress((void**)&wa2, gwa2);
    cudaGetSymbolAddress((void**)&wasc, gwasc);
    cudaGetSymbolAddress((void**)&wp1, gwp1); cudaGetSymbolAddress((void**)&wp2, gwp2);
    cudaGetSymbolAddress((void**)&wpsc, gwpsc);
    cudaGetSymbolAddress((void**)&ah1, gah1); cudaGetSymbolAddress((void**)&ah2, gah2);
    cudaGetSymbolAddress((void**)&ahsc, gahsc);
    cudaGetSymbolAddress((void**)&gah, g_ah);

    cudaFuncSetAttribute(gemm_q8<0>, cudaFuncAttributeMaxDynamicSharedMemorySize, G8_SMEM);
    cudaFuncSetAttribute(gemm_q8<1>, cudaFuncAttributeMaxDynamicSharedMemorySize, G8_SMEM);
    cudaFuncSetAttribute(attn_q8, cudaFuncAttributeMaxDynamicSharedMemorySize, ATTN_SMEM);

    // 0) quantize inputs
    split_q8_rows<<<MROWS, 256>>>(x, x1, x2, xsc);
    colmax_k<<<N3 / 256, 256>>>(w_attn, wasc, N3);
    tq_k<<<dim3(N3 / 32, DD / 32), dim3(32, 8)>>>(w_attn, wa1, wa2, wasc, N3);
    colmax_k<<<DD / 256, 256>>>(w_proj, wpsc, DD);
    tq_k<<<dim3(DD / 32, DD / 32), dim3(32, 8)>>>(w_proj, wp1, wp2, wpsc, DD);

    // 1) QKV projection -> q/k int8 digits + scales, present fp32, v bf16
    gemm_q8<0><<<dim3(N3 / 128, MROWS / 128), 256, G8_SMEM>>>(
        x1, x2, xsc, wa1, wa2, wasc, b_attn, out);

    // 2) attention (includes upper-triangle zero fill) -> attn + g_ah
    attn_q8<<<dim3(SS / 128, HH, BB), 256, ATTN_SMEM>>>(out);

    // 3) quantize attn output rows, then output projection
    split_q8_rows<<<MROWS, 256>>>(gah, ah1, ah2, ahsc);
    gemm_q8<1><<<dim3(DD / 128, MROWS / 128), 256, G8_SMEM>>>(
        ah1, ah2, ahsc, wp1, wp2, wpsc, b_proj, out);
}

// round 11
// speedup vs baseline: 2.4666x; 2.4666x over previous
#include <cuda_runtime.h>
#include <cuda_bf16.h>
#include <cstdint>

// Problem constants
#define BB 2
#define SS 2048
#define DD 1024
#define HH 16
#define HD 64
#define N3 3072
#define MROWS 4096

// d_out layout
#define A_SZ   ((long long)BB * SS * DD)
#define P_HALF ((long long)BB * HH * SS * HD)
#define P_OFF  (A_SZ)
#define ATTN_OFF (A_SZ + 2 * P_HALF)

// Scratch (device globals)
__device__ __nv_bfloat16 g_xhi[MROWS * DD], g_xlo[MROWS * DD];
__device__ __nv_bfloat16 g_wahi[N3 * DD],  g_walo[N3 * DD];    // w_attn^T [3072,1024]
__device__ __nv_bfloat16 g_wphi[DD * DD],  g_wplo[DD * DD];    // w_proj^T [1024,1024]
__device__ __nv_bfloat16 g_ahhi[MROWS * DD], g_ahlo[MROWS * DD];
#define QKV_N (BB * HH * SS * HD)
__device__ __nv_bfloat16 g_qh[QKV_N], g_ql[QKV_N];
__device__ __nv_bfloat16 g_kh[QKV_N], g_kl[QKV_N];
__device__ __nv_bfloat16 g_vh[QKV_N], g_vl[QKV_N];

// ====================== base-PTX helpers ====================================
__device__ __forceinline__ uint32_t smem_u32(const void* p) {
    uint32_t a;
    asm("{ .reg .u64 t; cvta.to.shared.u64 t, %1; cvt.u32.u64 %0, t; }"
        : "=r"(a) : "l"(p));
    return a;
}
__device__ __forceinline__ void cpa16(uint32_t s, const void* g) {
    asm volatile("cp.async.cg.shared.global [%0], [%1], 16;" :: "r"(s), "l"(g));
}
#define CP_COMMIT() asm volatile("cp.async.commit_group;" ::: "memory")
#define CP_WAIT(n)  asm volatile("cp.async.wait_group %0;" :: "n"(n) : "memory")

__device__ __forceinline__ void ldsm4(uint32_t* r, uint32_t a) {
    asm volatile("ldmatrix.sync.aligned.m8n8.x4.shared.b16 {%0,%1,%2,%3}, [%4];"
                 : "=r"(r[0]), "=r"(r[1]), "=r"(r[2]), "=r"(r[3]) : "r"(a));
}
__device__ __forceinline__ void ldsm2(uint32_t* r, uint32_t a) {
    asm volatile("ldmatrix.sync.aligned.m8n8.x2.shared.b16 {%0,%1}, [%2];"
                 : "=r"(r[0]), "=r"(r[1]) : "r"(a));
}
__device__ __forceinline__ void ldsm2t(uint32_t* r, uint32_t a) {
    asm volatile("ldmatrix.sync.aligned.m8n8.x2.trans.shared.b16 {%0,%1}, [%2];"
                 : "=r"(r[0]), "=r"(r[1]) : "r"(a));
}
__device__ __forceinline__ void mma_bf16(float* d, const uint32_t* a, const uint32_t* b) {
    asm volatile("mma.sync.aligned.m16n8k16.row.col.f32.bf16.bf16.f32 "
                 "{%0,%1,%2,%3}, {%4,%5,%6,%7}, {%8,%9}, {%0,%1,%2,%3};"
                 : "+f"(d[0]), "+f"(d[1]), "+f"(d[2]), "+f"(d[3])
                 : "r"(a[0]), "r"(a[1]), "r"(a[2]), "r"(a[3]), "r"(b[0]), "r"(b[1]));
}
__device__ __forceinline__ void sp(float x, uint16_t& h, uint16_t& l) {
    __nv_bfloat16 bh = __float2bfloat16_rn(x);
    h = __bfloat16_as_ushort(bh);
    l = __bfloat16_as_ushort(__float2bfloat16_rn(x - __bfloat162float(bh)));
}
__device__ __forceinline__ uint32_t pk(uint16_t a, uint16_t b) {
    return (uint32_t)a | ((uint32_t)b << 16);
}

// ====================== bf16 split kernels ==================================
__global__ __launch_bounds__(256) void split_plain(const float* __restrict__ in,
                                                   __nv_bfloat16* __restrict__ hi,
                                                   __nv_bfloat16* __restrict__ lo, int n4) {
    int i = blockIdx.x * 256 + threadIdx.x;
    if (i >= n4) return;
    float4 v = ((const float4*)in)[i];
    uint16_t h0, h1, h2, h3, l0, l1, l2, l3;
    sp(v.x, h0, l0); sp(v.y, h1, l1); sp(v.z, h2, l2); sp(v.w, h3, l3);
    ((uint2*)hi)[i] = make_uint2(pk(h0, h1), pk(h2, h3));
    ((uint2*)lo)[i] = make_uint2(pk(l0, l1), pk(l2, l3));
}

__global__ __launch_bounds__(256) void split_T(const float* __restrict__ in,
                                               __nv_bfloat16* __restrict__ hi,
                                               __nv_bfloat16* __restrict__ lo, int N) {
    __shared__ float t[32][33];
    int nb = blockIdx.x * 32, kb = blockIdx.y * 32;
#pragma unroll
    for (int r = 0; r < 4; r++)
        t[threadIdx.y + r * 8][threadIdx.x] =
            in[(long long)(kb + threadIdx.y + r * 8) * N + nb + threadIdx.x];
    __syncthreads();
#pragma unroll
    for (int r = 0; r < 4; r++) {
        int n = nb + threadIdx.y + r * 8;
        float v = t[threadIdx.x][threadIdx.y + r * 8];
        uint16_t h, l;
        sp(v, h, l);
        long long o = (long long)n * 1024 + kb + threadIdx.x;
        hi[o] = __ushort_as_bfloat16(h);
        lo[o] = __ushort_as_bfloat16(l);
    }
}

// ====================== pipelined mma.sync GEMM (bf16x3) ====================
// K-chunk 32 per stage -> stage 40KB, double buffered 80KB -> 2 CTAs/SM.
#define GPB 80
#define GT_TILEB (128 * GPB)           // 10240
#define GT_STAGEB (4 * GT_TILEB)       // 40960
#define GEMM_SMEM (2 * GT_STAGEB)      // 81920

template <int MODE>
__global__ __launch_bounds__(256, 2) void gemm_mma(
    const __nv_bfloat16* __restrict__ Ahi, const __nv_bfloat16* __restrict__ Alo,
    const __nv_bfloat16* __restrict__ Bhi, const __nv_bfloat16* __restrict__ Blo,
    const float* __restrict__ bias, float* __restrict__ out) {
    extern __shared__ char smm[];
    const uint32_t sb = smem_u32(smm);
    const int tid = threadIdx.x;
    const int lane = tid & 31, warp = tid >> 5;
    const int wm = warp >> 1, wn = warp & 1;
    const int qr = lane >> 2, qc2 = (lane & 3) * 2;
    const int nbase = blockIdx.x * 128, rbase = blockIdx.y * 128;

    float o[2][8][4];
#pragma unroll
    for (int a = 0; a < 2; a++)
#pragma unroll
        for (int b = 0; b < 8; b++)
#pragma unroll
            for (int c = 0; c < 4; c++) o[a][b][c] = 0.f;

    const char* srcs[4] = {
        (const char*)(Ahi + (long long)rbase * 1024),
        (const char*)(Alo + (long long)rbase * 1024),
        (const char*)(Bhi + (long long)nbase * 1024),
        (const char*)(Blo + (long long)nbase * 1024)};

    // prologue: load stage 0 (4 tiles x 128 rows x 64B = 2048 16B-chunks)
#pragma unroll
    for (int i = 0; i < 8; i++) {
        int idx = tid + i * 256;
        int t = idx >> 9, q = idx & 511, r = q >> 2, c = q & 3;
        cpa16(sb + t * GT_TILEB + r * GPB + c * 16,
              srcs[t] + (long long)r * 2048 + c * 16);
    }
    CP_COMMIT();

    for (int ks = 0; ks < 32; ks++) {
        if (ks + 1 < 32) {
            const int kboff = (ks + 1) * 64;   // bytes into K row
            const uint32_t dstb = sb + ((ks + 1) & 1) * GT_STAGEB;
#pragma unroll
            for (int i = 0; i < 8; i++) {
                int idx = tid + i * 256;
                int t = idx >> 9, q = idx & 511, r = q >> 2, c = q & 3;
                cpa16(dstb + t * GT_TILEB + r * GPB + c * 16,
                      srcs[t] + (long long)r * 2048 + kboff + c * 16);
            }
            CP_COMMIT();
            CP_WAIT(1);
        } else {
            CP_WAIT(0);
        }
        __syncthreads();

        const uint32_t base = sb + (ks & 1) * GT_STAGEB;
#pragma unroll
        for (int j = 0; j < 2; j++) {       // two k16 slices per 64B chunk
            uint32_t ah[2][4], al[2][4];
#pragma unroll
            for (int mt = 0; mt < 2; mt++) {
                uint32_t r = wm * 32 + mt * 16 + (lane & 7) + ((lane >> 3) & 1) * 8;
                uint32_t cb = j * 32 + (lane >> 4) * 16;
                uint32_t off = r * GPB + cb;
                ldsm4(ah[mt], base + off);
                ldsm4(al[mt], base + GT_TILEB + off);
            }
#pragma unroll
            for (int g = 0; g < 2; g++) {   // nt groups of 4 (reg pressure)
                uint32_t bh[4][2], bl[4][2];
#pragma unroll
                for (int u = 0; u < 4; u++) {
                    int nt = g * 4 + u;
                    uint32_t n = wn * 64 + nt * 8 + (lane & 7);
                    uint32_t cb = j * 32 + ((lane >> 3) & 1) * 16;
                    uint32_t off = n * GPB + cb;
                    ldsm2(bh[u], base + 2 * GT_TILEB + off);
                    ldsm2(bl[u], base + 3 * GT_TILEB + off);
                }
#pragma unroll
                for (int u = 0; u < 4; u++) {
                    mma_bf16(o[0][g * 4 + u], ah[0], bh[u]);
                    mma_bf16(o[1][g * 4 + u], ah[1], bh[u]);
                }
#pragma unroll
                for (int u = 0; u < 4; u++) {
                    mma_bf16(o[0][g * 4 + u], ah[0], bl[u]);
                    mma_bf16(o[1][g * 4 + u], ah[1], bl[u]);
                }
#pragma unroll
                for (int u = 0; u < 4; u++) {
                    mma_bf16(o[0][g * 4 + u], al[0], bh[u]);
                    mma_bf16(o[1][g * 4 + u], al[1], bh[u]);
                }
            }
        }
        __syncthreads();
    }

    // epilogue
#pragma unroll
    for (int nt = 0; nt < 8; nt++) {
        const int cg = nbase + wn * 64 + nt * 8 + qc2;
        const float b0 = bias[cg], b1 = bias[cg + 1];
#pragma unroll
        for (int mt = 0; mt < 2; mt++) {
            int r0 = rbase + wm * 32 + mt * 16 + qr;
            int r1 = r0 + 8;
            float2 v0 = make_float2(o[mt][nt][0] + b0, o[mt][nt][1] + b1);
            float2 v1 = make_float2(o[mt][nt][2] + b0, o[mt][nt][3] + b1);
            if (MODE == 0) {
                int which = cg >> 10, d0 = cg & 1023;
                int hh = d0 >> 6, e0 = d0 & 63;
                int b_0 = r0 >> 11, s_0 = r0 & 2047;
                int b_1 = r1 >> 11, s_1 = r1 & 2047;
                long long i0 = (((long long)(b_0 * HH + hh)) * SS + s_0) * HD + e0;
                long long i1 = (((long long)(b_1 * HH + hh)) * SS + s_1) * HD + e0;
                uint16_t h0, h1, h2, h3, l0, l1, l2, l3;
                sp(v0.x, h0, l0); sp(v0.y, h1, l1);
                sp(v1.x, h2, l2); sp(v1.y, h3, l3);
                if (which == 0) {
                    *(uint32_t*)&g_qh[i0] = pk(h0, h1); *(uint32_t*)&g_ql[i0] = pk(l0, l1);
                    *(uint32_t*)&g_qh[i1] = pk(h2, h3); *(uint32_t*)&g_ql[i1] = pk(l2, l3);
                } else if (which == 1) {
                    *(float2*)&out[P_OFF + i0] = v0;
                    *(float2*)&out[P_OFF + i1] = v1;
                    *(uint32_t*)&g_kh[i0] = pk(h0, h1); *(uint32_t*)&g_kl[i0] = pk(l0, l1);
                    *(uint32_t*)&g_kh[i1] = pk(h2, h3); *(uint32_t*)&g_kl[i1] = pk(l2, l3);
                } else {
                    *(float2*)&out[P_OFF + P_HALF + i0] = v0;
                    *(float2*)&out[P_OFF + P_HALF + i1] = v1;
                    *(uint32_t*)&g_vh[i0] = pk(h0, h1); *(uint32_t*)&g_vl[i0] = pk(l0, l1);
                    *(uint32_t*)&g_vh[i1] = pk(h2, h3); *(uint32_t*)&g_vl[i1] = pk(l2, l3);
                }
            } else {
                *(float2*)&out[(long long)r0 * DD + cg] = v0;
                *(float2*)&out[(long long)r1 * DD + cg] = v1;
            }
        }
    }
}

// ====================== attention (pipelined, 128-row Q tiles) ==============
#define APB 144
#define QT_B (128 * APB)
#define KT_B (64 * APB)
#define KSTAGE (4 * KT_B)
#define KBASE (2 * QT_B)
#define ATTN_SMEM (2 * QT_B + 2 * KSTAGE)   // 110592 -> 2 CTAs/SM

__global__ __launch_bounds__(256, 2) void attn_mma(float* __restrict__ out) {
    extern __shared__ char smm[];
    const uint32_t sb = smem_u32(smm);
    const int tid = threadIdx.x;
    const int lane = tid & 31, wm = tid >> 5;
    const int qr = lane >> 2, qc2 = (lane & 3) * 2;
    const int qt = (gridDim.x - 1) - blockIdx.x;
    const int h = blockIdx.y, b = blockIdx.z;
    const int qbase = qt * 128;
    const int bh_ = b * HH + h;
    const long long hoff = (long long)bh_ * SS * HD;
    const char* qhg = (const char*)(g_qh + hoff + (long long)qbase * HD);
    const char* qlg = (const char*)(g_ql + hoff + (long long)qbase * HD);
    const char* khg = (const char*)(g_kh + hoff);
    const char* klg = (const char*)(g_kl + hoff);
    const char* vhg = (const char*)(g_vh + hoff);
    const char* vlg = (const char*)(g_vl + hoff);
    float* attn_out = out + ATTN_OFF + (long long)bh_ * SS * SS;
    const int nkt = 2 * qt + 2;

#pragma unroll
    for (int i = 0; i < 4; i++) {
        int idx = tid + i * 256;
        int r = idx >> 3, c = idx & 7;
        cpa16(sb + r * APB + c * 16, qhg + idx * 16);
        cpa16(sb + QT_B + r * APB + c * 16, qlg + idx * 16);
    }
    CP_COMMIT();

#pragma unroll
    for (int i = 0; i < 2; i++) {
        int idx = tid + i * 256;
        int r = idx >> 3, c = idx & 7;
        cpa16(sb + KBASE + r * APB + c * 16, khg + idx * 16);
        cpa16(sb + KBASE + KT_B + r * APB + c * 16, klg + idx * 16);
    }
    CP_COMMIT();
    CP_WAIT(1);
    __syncthreads();

    uint32_t qh[4][4], ql[4][4];
#pragma unroll
    for (int j = 0; j < 4; j++) {
        uint32_t r = wm * 16 + (lane & 7) + ((lane >> 3) & 1) * 8;
        uint32_t c = j * 16 + (lane >> 4) * 8;
        uint32_t off = r * APB + c * 2;
        ldsm4(qh[j], sb + off);
        ldsm4(ql[j], sb + QT_B + off);
    }

    const int r0g = qbase + wm * 16 + qr;
    const int r1g = r0g + 8;

    // ---------------- pass A: rowsums ----------------
    float rs0 = 0.f, rs1 = 0.f;
    for (int kt = 0; kt < nkt; kt++) {
        if (kt + 1 < nkt) {
            const uint32_t db = sb + KBASE + ((kt + 1) & 1) * KSTAGE;
            const long long go = (long long)(kt + 1) * 8192;
#pragma unroll
            for (int i = 0; i < 2; i++) {
                int idx = tid + i * 256;
                int r = idx >> 3, c = idx & 7;
                cpa16(db + r * APB + c * 16, khg + go + idx * 16);
                cpa16(db + KT_B + r * APB + c * 16, klg + go + idx * 16);
            }
            CP_COMMIT();
            CP_WAIT(1);
        } else {
            CP_WAIT(0);
        }
        __syncthreads();

        const uint32_t kb = sb + KBASE + (kt & 1) * KSTAGE;
        float s[8][4];
#pragma unroll
        for (int nt = 0; nt < 8; nt++)
#pragma unroll
            for (int c = 0; c < 4; c++) s[nt][c] = 0.f;

#pragma unroll
        for (int j = 0; j < 4; j++) {
#pragma unroll
            for (int g = 0; g < 2; g++) {
                uint32_t bh2[4][2], bl2[4][2];
#pragma unroll
                for (int u = 0; u < 4; u++) {
                    uint32_t n = (g * 4 + u) * 8 + (lane & 7);
                    uint32_t c = j * 16 + ((lane >> 3) & 1) * 8;
                    uint32_t off = n * APB + c * 2;
                    ldsm2(bh2[u], kb + off);
                    ldsm2(bl2[u], kb + KT_B + off);
                }
#pragma unroll
                for (int u = 0; u < 4; u++) mma_bf16(s[g * 4 + u], qh[j], bh2[u]);
#pragma unroll
                for (int u = 0; u < 4; u++) mma_bf16(s[g * 4 + u], qh[j], bl2[u]);
#pragma unroll
                for (int u = 0; u < 4; u++) mma_bf16(s[g * 4 + u], ql[j], bh2[u]);
            }
        }
#pragma unroll
        for (int nt = 0; nt < 8; nt++) {
            const int cg = kt * 64 + nt * 8 + qc2;
            if (cg <= r0g)     rs0 += __expf(s[nt][0] * 0.125f);
            if (cg + 1 <= r0g) rs0 += __expf(s[nt][1] * 0.125f);
            if (cg <= r1g)     rs1 += __expf(s[nt][2] * 0.125f);
            if (cg + 1 <= r1g) rs1 += __expf(s[nt][3] * 0.125f);
        }
        __syncthreads();
    }
    rs0 += __shfl_xor_sync(0xFFFFFFFFu, rs0, 1);
    rs0 += __shfl_xor_sync(0xFFFFFFFFu, rs0, 2);
    rs1 += __shfl_xor_sync(0xFFFFFFFFu, rs1, 1);
    rs1 += __shfl_xor_sync(0xFFFFFFFFu, rs1, 2);
    const float ri0 = 1.0f / rs0;
    const float ri1 = 1.0f / rs1;

    // ---------------- pass B: write attn + A@V ----------------
    float o[8][4];
#pragma unroll
    for (int a = 0; a < 8; a++)
#pragma unroll
        for (int c = 0; c < 4; c++) o[a][c] = 0.f;

#pragma unroll
    for (int i = 0; i < 2; i++) {
        int idx = tid + i * 256;
        int r = idx >> 3, c = idx & 7;
        uint32_t db = sb + KBASE;
        cpa16(db + r * APB + c * 16, khg + idx * 16);
        cpa16(db + KT_B + r * APB + c * 16, klg + idx * 16);
        cpa16(db + 2 * KT_B + r * APB + c * 16, vhg + idx * 16);
        cpa16(db + 3 * KT_B + r * APB + c * 16, vlg + idx * 16);
    }
    CP_COMMIT();

    for (int kt = 0; kt < nkt; kt++) {
        if (kt + 1 < nkt) {
            const uint32_t db = sb + KBASE + ((kt + 1) & 1) * KSTAGE;
            const long long go = (long long)(kt + 1) * 8192;
#pragma unroll
            for (int i = 0; i < 2; i++) {
                int idx = tid + i * 256;
                int r = idx >> 3, c = idx & 7;
                cpa16(db + r * APB + c * 16, khg + go + idx * 16);
                cpa16(db + KT_B + r * APB + c * 16, klg + go + idx * 16);
                cpa16(db + 2 * KT_B + r * APB + c * 16, vhg + go + idx * 16);
                cpa16(db + 3 * KT_B + r * APB + c * 16, vlg + go + idx * 16);
            }
            CP_COMMIT();
            CP_WAIT(1);
        } else {
            CP_WAIT(0);
        }
        __syncthreads();

        const uint32_t kb = sb + KBASE + (kt & 1) * KSTAGE;
        float s[8][4];
#pragma unroll
        for (int nt = 0; nt < 8; nt++)
#pragma unroll
            for (int c = 0; c < 4; c++) s[nt][c] = 0.f;
#pragma unroll
        for (int j = 0; j < 4; j++) {
#pragma unroll
            for (int g = 0; g < 2; g++) {
                uint32_t bh2[4][2], bl2[4][2];
#pragma unroll
                for (int u = 0; u < 4; u++) {
                    uint32_t n = (g * 4 + u) * 8 + (lane & 7);
                    uint32_t c = j * 16 + ((lane >> 3) & 1) * 8;
                    uint32_t off = n * APB + c * 2;
                    ldsm2(bh2[u], kb + off);
                    ldsm2(bl2[u], kb + KT_B + off);
                }
#pragma unroll
                for (int u = 0; u < 4; u++) mma_bf16(s[g * 4 + u], qh[j], bh2[u]);
#pragma unroll
                for (int u = 0; u < 4; u++) mma_bf16(s[g * 4 + u], qh[j], bl2[u]);
#pragma unroll
                for (int u = 0; u < 4; u++) mma_bf16(s[g * 4 + u], ql[j], bh2[u]);
            }
        }

        uint32_t sah[4][4], sal[4][4];
#pragma unroll
        for (int nt = 0; nt < 8; nt++) {
            const int cg = kt * 64 + nt * 8 + qc2;
            float e0 = (cg > r0g)     ? 0.f : __expf(s[nt][0] * 0.125f) * ri0;
            float e1 = (cg + 1 > r0g) ? 0.f : __expf(s[nt][1] * 0.125f) * ri0;
            float e2 = (cg > r1g)     ? 0.f : __expf(s[nt][2] * 0.125f) * ri1;
            float e3 = (cg + 1 > r1g) ? 0.f : __expf(s[nt][3] * 0.125f) * ri1;
            *(float2*)&attn_out[(long long)r0g * SS + cg] = make_float2(e0, e1);
            *(float2*)&attn_out[(long long)r1g * SS + cg] = make_float2(e2, e3);
            uint16_t h0, h1, h2, h3, l0, l1, l2, l3;
            sp(e0, h0, l0); sp(e1, h1, l1); sp(e2, h2, l2); sp(e3, h3, l3);
            const int j = nt >> 1, half = (nt & 1) * 2;
            sah[j][half] = pk(h0, h1); sah[j][half + 1] = pk(h2, h3);
            sal[j][half] = pk(l0, l1); sal[j][half + 1] = pk(l2, l3);
        }
        // A@V
#pragma unroll
        for (int j = 0; j < 4; j++) {
#pragma unroll
            for (int g = 0; g < 2; g++) {
                uint32_t vh2[4][2], vl2[4][2];
#pragma unroll
                for (int u = 0; u < 4; u++) {
                    uint32_t key = j * 16 + ((lane >> 3) & 1) * 8 + (lane & 7);
                    uint32_t off = key * APB + (g * 4 + u) * 16;
                    ldsm2t(vh2[u], kb + 2 * KT_B + off);
                    ldsm2t(vl2[u], kb + 3 * KT_B + off);
                }
#pragma unroll
                for (int u = 0; u < 4; u++) mma_bf16(o[g * 4 + u], sah[j], vh2[u]);
#pragma unroll
                for (int u = 0; u < 4; u++) mma_bf16(o[g * 4 + u], sah[j], vl2[u]);
#pragma unroll
                for (int u = 0; u < 4; u++) mma_bf16(o[g * 4 + u], sal[j], vh2[u]);
            }
        }
        __syncthreads();
    }

    // write merged-head output directly as bf16 hi/lo (feeds proj GEMM)
#pragma unroll
    for (int nt2 = 0; nt2 < 8; nt2++) {
        const int col = h * 64 + nt2 * 8 + qc2;
        const long long gr0 = (long long)(b * SS + qbase + wm * 16 + qr);
        uint16_t h0, h1, h2, h3, l0, l1, l2, l3;
        sp(o[nt2][0], h0, l0); sp(o[nt2][1], h1, l1);
        sp(o[nt2][2], h2, l2); sp(o[nt2][3], h3, l3);
        *(uint32_t*)&g_ahhi[gr0 * DD + col] = pk(h0, h1);
        *(uint32_t*)&g_ahlo[gr0 * DD + col] = pk(l0, l1);
        *(uint32_t*)&g_ahhi[(gr0 + 8) * DD + col] = pk(h2, h3);
        *(uint32_t*)&g_ahlo[(gr0 + 8) * DD + col] = pk(l2, l3);
    }
}

// ====================== upper-triangle zero fill ============================
__global__ __launch_bounds__(256) void attn_fill(float* __restrict__ out) {
    const int tid = threadIdx.x;
    const int qt = blockIdx.x, bh = blockIdx.y;
    const int Lc = (qt + 1) * 128;
    const int per4 = (SS - Lc) >> 2;
    if (per4 == 0) return;
    float* base = out + ATTN_OFF + (long long)bh * SS * SS + (long long)qt * 128 * SS;
    const float4 z = make_float4(0.f, 0.f, 0.f, 0.f);
    for (int i = tid; i < 128 * per4; i += 256) {
        int r = i / per4;
        int c = Lc + (i - r * per4) * 4;
        *(float4*)&base[(long long)r * SS + c] = z;
    }
}

// ====================== launch ==============================================
extern "C" void kernel_launch(void* const* d_in, const int* in_sizes, int n_in,
                              void* d_out, int out_size) {
    const float* x      = (const float*)d_in[0];
    const float* w_attn = (const float*)d_in[1];
    const float* b_attn = (const float*)d_in[2];
    const float* w_proj = (const float*)d_in[3];
    const float* b_proj = (const float*)d_in[4];
    float* out = (float*)d_out;

    __nv_bfloat16 *xhi, *xlo, *wahi, *walo, *wphi, *wplo, *ahhi, *ahlo;
    cudaGetSymbolAddress((void**)&xhi,  g_xhi);
    cudaGetSymbolAddress((void**)&xlo,  g_xlo);
    cudaGetSymbolAddress((void**)&wahi, g_wahi);
    cudaGetSymbolAddress((void**)&walo, g_walo);
    cudaGetSymbolAddress((void**)&wphi, g_wphi);
    cudaGetSymbolAddress((void**)&wplo, g_wplo);
    cudaGetSymbolAddress((void**)&ahhi, g_ahhi);
    cudaGetSymbolAddress((void**)&ahlo, g_ahlo);

    cudaFuncSetAttribute(gemm_mma<0>, cudaFuncAttributeMaxDynamicSharedMemorySize, GEMM_SMEM);
    cudaFuncSetAttribute(gemm_mma<1>, cudaFuncAttributeMaxDynamicSharedMemorySize, GEMM_SMEM);
    cudaFuncSetAttribute(attn_mma, cudaFuncAttributeMaxDynamicSharedMemorySize, ATTN_SMEM);

    split_plain<<<(MROWS * DD / 4 + 255) / 256, 256>>>(x, xhi, xlo, MROWS * DD / 4);
    split_T<<<dim3(N3 / 32, DD / 32), dim3(32, 8)>>>(w_attn, wahi, walo, N3);
    split_T<<<dim3(DD / 32, DD / 32), dim3(32, 8)>>>(w_proj, wphi, wplo, DD);

    gemm_mma<0><<<dim3(N3 / 128, MROWS / 128), 256, GEMM_SMEM>>>(xhi, xlo, wahi, walo, b_attn, out);

    attn_mma<<<dim3(SS / 128, HH, BB), 256, ATTN_SMEM>>>(out);

    attn_fill<<<dim3(SS / 128, BB * HH), 256>>>(out);

    gemm_mma<1><<<dim3(DD / 128, MROWS / 128), 256, GEMM_SMEM>>>(ahhi, ahlo, wphi, wplo, b_proj, out);
}